// round 1
// baseline (speedup 1.0000x reference)
#include <cuda_runtime.h>

#define NB 8
#define NC 10
#define NH 192
#define NW 192
#define HW (NH*NW)
#define CHW (NC*HW)

#define TX 32
#define TY 8
#define TW_ (TX+2)
#define TH_ (TY+2)
#define TSZ (TW_*TH_)
#define WPAD 12

// ---------------- scratch (static device globals; no allocation) ----------------
__device__ float g_a1[NB*CHW];     // f1 * att[:,1]
__device__ float g_a2[NB*CHW];     // f1 * att[:,2]
__device__ float g_mapu[NB*HW];    // sigmoid comp map upper
__device__ float g_mapl[NB*HW];    // sigmoid comp map lower
__device__ float g_msgu[NB*CHW];   // msg_u = d0 + comp_u
__device__ float g_msgl[NB*CHW];   // msg_l = d1 + comp_l

__device__ __forceinline__ float sigmoidf_(float x){ return 1.0f/(1.0f+expf(-x)); }

// ================= Kernel 1: pointwise attention / maps =================
__global__ __launch_bounds__(256) void k1_pointwise(
    const float* __restrict__ f_nodes,
    const float* __restrict__ h_nodes,
    const float* __restrict__ p_nodes,
    const float* __restrict__ w_dmap, const float* __restrict__ b_dmap,
    const float* __restrict__ w_cau,  const float* __restrict__ b_cau,
    const float* __restrict__ w_cal,  const float* __restrict__ b_cal,
    float* __restrict__ out_decomp, float* __restrict__ out_cmu, float* __restrict__ out_cml)
{
    __shared__ float s_wd[90], s_bd[3], s_wcau[40], s_wcal[20], s_bc[2];
    int t = threadIdx.x;
    if (t < 90)            s_wd[t]       = w_dmap[t];
    if (t >= 96 && t < 99) s_bd[t-96]    = b_dmap[t-96];
    if (t >= 128 && t < 168) s_wcau[t-128] = w_cau[t-128];
    if (t >= 192 && t < 212) s_wcal[t-192] = w_cal[t-192];
    if (t == 224) s_bc[0] = b_cau[0];
    if (t == 225) s_bc[1] = b_cal[0];
    __syncthreads();

    int pix = blockIdx.x*256 + t;              // < NB*HW (exact multiple)
    int b = pix / HW, p = pix - b*HW;

    const float* f1 = f_nodes + (size_t)(1*NB + b)*CHW + p;
    const float* h1 = h_nodes + (size_t)(1*NB + b)*CHW + p;
    const float* h2 = h_nodes + (size_t)(2*NB + b)*CHW + p;

    float f[10], u1[10], u2[10];
    #pragma unroll
    for (int c=0;c<10;c++){ f[c]=f1[c*HW]; u1[c]=h1[c*HW]; u2[c]=h2[c*HW]; }

    float dm0=s_bd[0], dm1=s_bd[1], dm2=s_bd[2];
    #pragma unroll
    for (int c=0;c<10;c++){
        dm0 = fmaf(s_wd[ 0+c],f[c],dm0); dm0 = fmaf(s_wd[10+c],u1[c],dm0); dm0 = fmaf(s_wd[20+c],u2[c],dm0);
        dm1 = fmaf(s_wd[30+c],f[c],dm1); dm1 = fmaf(s_wd[40+c],u1[c],dm1); dm1 = fmaf(s_wd[50+c],u2[c],dm1);
        dm2 = fmaf(s_wd[60+c],f[c],dm2); dm2 = fmaf(s_wd[70+c],u1[c],dm2); dm2 = fmaf(s_wd[80+c],u2[c],dm2);
    }
    // softmax over the 3 channels
    float mx = fmaxf(dm0, fmaxf(dm1, dm2));
    float e0 = expf(dm0-mx), e1 = expf(dm1-mx), e2 = expf(dm2-mx);
    float inv = 1.0f/(e0+e1+e2);
    float att1 = e1*inv, att2 = e2*inv;

    float* a1p = g_a1 + (size_t)b*CHW + p;
    float* a2p = g_a2 + (size_t)b*CHW + p;
    #pragma unroll
    for (int c=0;c<10;c++){ a1p[c*HW] = f[c]*att1; a2p[c*HW] = f[c]*att2; }

    out_decomp[(size_t)(b*3+0)*HW + p] = dm0;
    out_decomp[(size_t)(b*3+1)*HW + p] = dm1;
    out_decomp[(size_t)(b*3+2)*HW + p] = dm2;

    // comp_map_u: 1x1 conv over parts 1..4 (40 ch) -> sigmoid
    float su = s_bc[0];
    #pragma unroll
    for (int j=0;j<4;j++){
        const float* pp = p_nodes + (size_t)((j+1)*NB + b)*CHW + p;
        #pragma unroll
        for (int c=0;c<10;c++) su = fmaf(s_wcau[j*10+c], pp[c*HW], su);
    }
    float mu = sigmoidf_(su);
    g_mapu[(size_t)b*HW + p] = mu;
    out_cmu[(size_t)b*HW + p] = mu;

    // comp_map_l: parts 5..6 (20 ch)
    float sl = s_bc[1];
    #pragma unroll
    for (int j=0;j<2;j++){
        const float* pp = p_nodes + (size_t)((j+5)*NB + b)*CHW + p;
        #pragma unroll
        for (int c=0;c<10;c++) sl = fmaf(s_wcal[j*10+c], pp[c*HW], sl);
    }
    float ml = sigmoidf_(sl);
    g_mapl[(size_t)b*HW + p] = ml;
    out_cml[(size_t)b*HW + p] = ml;
}

// ================= Kernel 2: fused 3x3 convs -> msg =================
// weight smem layout: s_w[(ci*9+k)*WPAD + o] so one scalar v feeds 10 FMAs via
// vectorized broadcast loads (float4/float4/float2).
__device__ __forceinline__ void conv_acc(float* acc, const float (*tile)[TSZ],
                                         const float* swt, int cibase, int tx, int ty)
{
    #pragma unroll 1
    for (int ci=0; ci<10; ci++){
        float v[9];
        #pragma unroll
        for (int dy=0; dy<3; dy++){
            #pragma unroll
            for (int dx=0; dx<3; dx++)
                v[dy*3+dx] = tile[ci][(ty+dy)*TW_ + tx+dx];
        }
        const float* wb = swt + (cibase+ci)*9*WPAD;
        #pragma unroll
        for (int k=0; k<9; k++){
            float4 wa = *(const float4*)(wb + k*WPAD);
            float4 w2 = *(const float4*)(wb + k*WPAD + 4);
            float2 w3 = *(const float2*)(wb + k*WPAD + 8);
            float vv = v[k];
            acc[0]=fmaf(wa.x,vv,acc[0]); acc[1]=fmaf(wa.y,vv,acc[1]);
            acc[2]=fmaf(wa.z,vv,acc[2]); acc[3]=fmaf(wa.w,vv,acc[3]);
            acc[4]=fmaf(w2.x,vv,acc[4]); acc[5]=fmaf(w2.y,vv,acc[5]);
            acc[6]=fmaf(w2.z,vv,acc[6]); acc[7]=fmaf(w2.w,vv,acc[7]);
            acc[8]=fmaf(w3.x,vv,acc[8]); acc[9]=fmaf(w3.y,vv,acc[9]);
        }
    }
}

__global__ __launch_bounds__(256) void k2_conv(
    const float* __restrict__ h_nodes, const float* __restrict__ p_nodes,
    const float* __restrict__ w_decomp, const float* __restrict__ g_decomp, const float* __restrict__ be_decomp,
    const float* __restrict__ w_cu, const float* __restrict__ g_cu, const float* __restrict__ be_cu,
    const float* __restrict__ w_cl, const float* __restrict__ g_cl, const float* __restrict__ be_cl)
{
    __shared__ __align__(16) float s_wdt[180*WPAD];
    __shared__ __align__(16) float s_wct[180*WPAD];
    __shared__ float s_tile[10][TSZ];
    __shared__ float s_map[TSZ];
    __shared__ float s_gd[10], s_bed[10], s_gc[10], s_bec[10];

    int z = blockIdx.z; int b = z >> 1; int half = z & 1;
    const float* wc   = half ? w_cl  : w_cu;
    const float* gcv  = half ? g_cl  : g_cu;
    const float* becv = half ? be_cl : be_cu;
    const float* aX   = (half ? g_a2 : g_a1) + (size_t)b*CHW;
    const float* hX   = h_nodes + (size_t)((half?2:1)*NB + b)*CHW;
    const float* mapX = (half ? g_mapl : g_mapu) + (size_t)b*HW;
    float* msg        = (half ? g_msgl : g_msgu) + (size_t)b*CHW;
    int nparts = half ? 2 : 4;
    int pbase  = half ? 5 : 1;

    int tid = threadIdx.y*TX + threadIdx.x;
    for (int i=tid; i<1800; i+=256){
        int o = i/180, r = i - o*180, c = r/9, k = r - c*9;
        s_wdt[(c*9+k)*WPAD + o] = w_decomp[i];
        s_wct[(c*9+k)*WPAD + o] = wc[i];
    }
    if (tid < 10){
        s_gd[tid]=g_decomp[tid]; s_bed[tid]=be_decomp[tid];
        s_gc[tid]=gcv[tid];      s_bec[tid]=becv[tid];
    }

    int x0 = blockIdx.x*TX, y0 = blockIdx.y*TY;

    // map tile (with halo)
    for (int j=tid; j<TSZ; j+=256){
        int r=j/TW_, c=j-r*TW_;
        int gy=y0-1+r, gx=x0-1+c;
        s_map[j] = (gy>=0 && gy<NH && gx>=0 && gx<NW) ? mapX[gy*NW+gx] : 0.0f;
    }
    // a tile group
    for (int i=tid; i<10*TSZ; i+=256){
        int ci=i/TSZ, j=i-ci*TSZ;
        int r=j/TW_, c=j-r*TW_;
        int gy=y0-1+r, gx=x0-1+c;
        s_tile[ci][j] = (gy>=0 && gy<NH && gx>=0 && gx<NW) ? aX[(size_t)ci*HW + gy*NW + gx] : 0.0f;
    }
    __syncthreads();

    int tx = threadIdx.x, ty = threadIdx.y;
    float accD[10];
    #pragma unroll
    for (int o=0;o<10;o++) accD[o]=0.0f;
    conv_acc(accD, s_tile, s_wdt, 0, tx, ty);           // w_decomp[:, 0:10] * (f*att)
    __syncthreads();

    // h tile group
    for (int i=tid; i<10*TSZ; i+=256){
        int ci=i/TSZ, j=i-ci*TSZ;
        int r=j/TW_, c=j-r*TW_;
        int gy=y0-1+r, gx=x0-1+c;
        s_tile[ci][j] = (gy>=0 && gy<NH && gx>=0 && gx<NW) ? hX[(size_t)ci*HW + gy*NW + gx] : 0.0f;
    }
    __syncthreads();
    conv_acc(accD, s_tile, s_wdt, 10, tx, ty);          // w_decomp[:, 10:20] * h
    float accA[10];
    #pragma unroll
    for (int o=0;o<10;o++) accA[o]=0.0f;
    conv_acc(accA, s_tile, s_wct, 0, tx, ty);           // shared A = w_c[:, 0:10] * h

    float msgv[10];
    #pragma unroll
    for (int o=0;o<10;o++)
        msgv[o] = fmaxf(fmaf(s_gd[o], accD[o], s_bed[o]), 0.0f);   // d term

    for (int part=0; part<nparts; part++){
        const float* pX = p_nodes + (size_t)((pbase+part)*NB + b)*CHW;
        __syncthreads();
        for (int i=tid; i<10*TSZ; i+=256){
            int ci=i/TSZ, j=i-ci*TSZ;
            int r=j/TW_, c=j-r*TW_;
            int gy=y0-1+r, gx=x0-1+c;
            s_tile[ci][j] = (gy>=0 && gy<NH && gx>=0 && gx<NW)
                          ? pX[(size_t)ci*HW + gy*NW + gx] * s_map[j] : 0.0f;
        }
        __syncthreads();
        float acc[10];
        #pragma unroll
        for (int o=0;o<10;o++) acc[o]=accA[o];
        conv_acc(acc, s_tile, s_wct, 10, tx, ty);       // w_c[:, 10:20] * (p*map)
        #pragma unroll
        for (int o=0;o<10;o++)
            msgv[o] += fmaxf(fmaf(s_gc[o], acc[o], s_bec[o]), 0.0f);
    }

    int px = x0+tx, py = y0+ty;
    #pragma unroll
    for (int o=0;o<10;o++)
        msg[(size_t)o*HW + py*NW + px] = msgv[o];
}

// ================= Kernel 3: pointwise ConvGRU + slot-0 copy =================
__global__ __launch_bounds__(256) void k3_gru(
    const float* __restrict__ h_nodes,
    const float* __restrict__ wg_u, const float* __restrict__ bg_u,
    const float* __restrict__ wc_u, const float* __restrict__ g_u, const float* __restrict__ be_u,
    const float* __restrict__ wg_l, const float* __restrict__ bg_l,
    const float* __restrict__ wc_l, const float* __restrict__ g_l, const float* __restrict__ be_l,
    float* __restrict__ out_xh)
{
    int half = blockIdx.y;
    __shared__ float s_wg[40], s_bg[2], s_wc[200], s_g[10], s_be[10];
    const float* wg = half ? wg_l : wg_u;
    const float* bg = half ? bg_l : bg_u;
    const float* wc = half ? wc_l : wc_u;
    const float* gg = half ? g_l  : g_u;
    const float* be = half ? be_l : be_u;
    int t = threadIdx.x;
    if (t < 40) s_wg[t] = wg[t];
    if (t >= 64 && t < 66) s_bg[t-64] = bg[t-64];
    if (t >= 70 && t < 80) s_g[t-70]  = gg[t-70];
    if (t >= 80 && t < 90) s_be[t-80] = be[t-80];
    if (t < 200) s_wc[t] = wc[t];
    __syncthreads();

    int pix = blockIdx.x*256 + t;
    int b = pix / HW, p = pix - b*HW;

    const float* msg = (half ? g_msgl : g_msgu) + (size_t)b*CHW + p;
    const float* hp  = h_nodes + (size_t)((half?2:1)*NB + b)*CHW + p;

    float m[10], hh[10];
    #pragma unroll
    for (int c=0;c<10;c++){ m[c]=msg[c*HW]; hh[c]=hp[c*HW]; }

    float g0 = s_bg[0], g1 = s_bg[1];
    #pragma unroll
    for (int c=0;c<10;c++){
        g0 = fmaf(s_wg[c],    m[c],  g0);
        g0 = fmaf(s_wg[10+c], hh[c], g0);
        g1 = fmaf(s_wg[20+c], m[c],  g1);
        g1 = fmaf(s_wg[30+c], hh[c], g1);
    }
    float r = sigmoidf_(g0), u = sigmoidf_(g1);
    float rh[10];
    #pragma unroll
    for (int c=0;c<10;c++) rh[c] = r*hh[c];

    float* op = out_xh + (size_t)((half?2:1)*NB + b)*CHW + p;
    #pragma unroll
    for (int o=0;o<10;o++){
        float s = 0.0f;
        #pragma unroll
        for (int c=0;c<10;c++){
            s = fmaf(s_wc[o*20+c],    m[c],  s);
            s = fmaf(s_wc[o*20+10+c], rh[c], s);
        }
        float cn = fmaf(s_g[o], s, s_be[o]);
        cn = cn > 0.0f ? cn : 0.01f*cn;                 // leaky_relu 0.01
        op[o*HW] = (1.0f-u)*hh[o] + u*cn;
    }

    if (!half){
        const float* h0 = h_nodes + (size_t)b*CHW + p;
        float* o0 = out_xh + (size_t)b*CHW + p;         // slot 0 of xh_new
        #pragma unroll
        for (int c=0;c<10;c++) o0[c*HW] = h0[c*HW];
    }
}

// ================= launcher =================
extern "C" void kernel_launch(void* const* d_in, const int* in_sizes, int n_in,
                              void* d_out, int out_size)
{
    const float* f_nodes  = (const float*)d_in[0];
    const float* h_nodes  = (const float*)d_in[1];
    const float* p_nodes  = (const float*)d_in[2];
    // d_in[3] = xh (unused by reference)
    const float* w_dmap   = (const float*)d_in[4];
    const float* b_dmap   = (const float*)d_in[5];
    const float* w_decomp = (const float*)d_in[6];
    const float* g_decomp = (const float*)d_in[7];
    const float* be_decomp= (const float*)d_in[8];
    const float* w_cau    = (const float*)d_in[9];
    const float* b_cau    = (const float*)d_in[10];
    const float* w_cal    = (const float*)d_in[11];
    const float* b_cal    = (const float*)d_in[12];
    const float* w_cu     = (const float*)d_in[13];
    const float* g_cu     = (const float*)d_in[14];
    const float* be_cu    = (const float*)d_in[15];
    const float* w_cl     = (const float*)d_in[16];
    const float* g_cl     = (const float*)d_in[17];
    const float* be_cl    = (const float*)d_in[18];
    const float* wg_u     = (const float*)d_in[19];
    const float* bg_u     = (const float*)d_in[20];
    const float* wc_u     = (const float*)d_in[21];
    const float* g_u      = (const float*)d_in[22];
    const float* be_u     = (const float*)d_in[23];
    const float* wg_l     = (const float*)d_in[24];
    const float* bg_l     = (const float*)d_in[25];
    const float* wc_l     = (const float*)d_in[26];
    const float* g_l      = (const float*)d_in[27];
    const float* be_l     = (const float*)d_in[28];

    float* out        = (float*)d_out;
    float* out_decomp = out + (size_t)3*NB*CHW;      // xh_new is 3*B*10*H*W
    float* out_cmu    = out_decomp + (size_t)NB*3*HW;
    float* out_cml    = out_cmu + (size_t)NB*HW;

    k1_pointwise<<<NB*HW/256, 256>>>(f_nodes, h_nodes, p_nodes,
                                     w_dmap, b_dmap, w_cau, b_cau, w_cal, b_cal,
                                     out_decomp, out_cmu, out_cml);

    dim3 g2(NW/TX, NH/TY, 2*NB), b2(TX, TY);
    k2_conv<<<g2, b2>>>(h_nodes, p_nodes,
                        w_decomp, g_decomp, be_decomp,
                        w_cu, g_cu, be_cu,
                        w_cl, g_cl, be_cl);

    k3_gru<<<dim3(NB*HW/256, 2), 256>>>(h_nodes,
                                        wg_u, bg_u, wc_u, g_u, be_u,
                                        wg_l, bg_l, wc_l, g_l, be_l,
                                        out);
}